// round 8
// baseline (speedup 1.0000x reference)
#include <cuda_runtime.h>
#include <math.h>

// EdgeAttr: out[e][c] = sigmoid( sum_k exp(-(((d_e - 0.4k)/0.375)^2)) * W[k][c] + b[c] )
// Inputs: pos [N,3] f32, edge_index [2,E] int32, W [16,128] f32, b [128] f32
// Output: [E,128] f32
//
// R8: edge-pair f32x2 packing. Accumulator = (edge_a, edge_b) for one column;
//     multiplicand (r_a,r_b) comes packed straight from a transposed smem tile
//     (LDS.64 broadcast, no MOVs). W duplicated (w,w) into regs once per block.
//     Lane owns 2 columns (32 packed W regs), 2 warps cover an edge-pair's 128 cols.
//     launch_bounds(256,3) for higher occupancy.

#define THREADS 256
#define E_TILE  64
#define E_PAD   68          // padded edge stride (floats) -> conflict-free phase-1 stores
#define HID     128
#define DC      16

__device__ __forceinline__ unsigned long long pack2(float lo, float hi) {
    unsigned long long r;
    asm("mov.b64 %0, {%1, %2};" : "=l"(r) : "f"(lo), "f"(hi));
    return r;
}
__device__ __forceinline__ void unpack2(unsigned long long v, float& lo, float& hi) {
    asm("mov.b64 {%0, %1}, %2;" : "=f"(lo), "=f"(hi) : "l"(v));
}
__device__ __forceinline__ unsigned long long fma2(unsigned long long a,
                                                   unsigned long long b,
                                                   unsigned long long c) {
    unsigned long long d;
    asm("fma.rn.f32x2 %0, %1, %2, %3;" : "=l"(d) : "l"(a), "l"(b), "l"(c));
    return d;
}
__device__ __forceinline__ float fast_sigmoid(float x) {
    // 1 / (1 + 2^(-x*log2e)) : 2 MUFU + 1 FMUL + 1 FADD  (proven)
    float e, r;
    asm("ex2.approx.f32 %0, %1;" : "=f"(e) : "f"(-1.4426950408889634f * x));
    asm("rcp.approx.f32 %0, %1;" : "=f"(r) : "f"(1.0f + e));
    return r;
}

__global__ __launch_bounds__(THREADS, 3)
void edge_attr_kernel(const float* __restrict__ pos,
                      const int* __restrict__ edge_index,
                      const float* __restrict__ W,
                      const float* __restrict__ bias,
                      float* __restrict__ out,
                      int n_edges, int n_tiles)
{
    // Transposed RBF tile: sRT[buf][k][edge], padded stride. 2*16*68*4 = 8704 B.
    __shared__ float sRT[2][DC][E_PAD];

    const int t    = threadIdx.x;
    const int lane = t & 31;
    const int w    = t >> 5;          // warp 0..7
    const int half = w & 1;           // column half: 0 -> cols [0,64), 1 -> [64,128)
    const int pg   = w >> 1;          // pair-group 0..3: edges [pg*16, pg*16+16)
    const int c    = half * 64 + lane * 2;   // this lane's 2 output columns

    // ---- duplicated W slice + bias into registers (once per block) ----
    unsigned long long wd[2 * DC];    // wd[2k]=(W[k][c],W[k][c]), wd[2k+1]=(W[k][c+1],W[k][c+1])
    #pragma unroll
    for (int kk = 0; kk < DC; kk++) {
        const float2 wv = *reinterpret_cast<const float2*>(W + kk * HID + c);
        wd[2 * kk]     = pack2(wv.x, wv.x);
        wd[2 * kk + 1] = pack2(wv.y, wv.y);
    }
    unsigned long long bd0, bd1;
    {
        const float2 bv = *reinterpret_cast<const float2*>(bias + c);
        bd0 = pack2(bv.x, bv.x);
        bd1 = pack2(bv.y, bv.y);
    }

    // Phase-1 role: 4 threads per edge, each computes 4 RBF terms
    const int el = t >> 2;            // local edge 0..63
    const int q  = t & 3;             // quarter 0..3
    const long long stride = gridDim.x;

    // ---- gather pipeline registers (2-deep: idx ahead of pos) ----
    int   ia2, ib2;
    float pax, pay, paz, pbx, pby, pbz;

    long long tile = blockIdx.x;
    {   // prologue: pos for tile, idx for tile+stride
        int ge = (int)min(tile * E_TILE + el, (long long)n_edges - 1);
        const int ia = edge_index[ge];
        const int ib = edge_index[n_edges + ge];
        pax = pos[3 * ia]; pay = pos[3 * ia + 1]; paz = pos[3 * ia + 2];
        pbx = pos[3 * ib]; pby = pos[3 * ib + 1]; pbz = pos[3 * ib + 2];
        int ge2 = (int)min((tile + stride) * E_TILE + el, (long long)n_edges - 1);
        ia2 = edge_index[ge2];
        ib2 = edge_index[n_edges + ge2];
    }

    int buf = 0;
    for (; tile < n_tiles; tile += stride) {
        // ---- phase 1: RBF for current tile -> transposed smem ----
        {
            const float dx = pax - pbx, dy = pay - pby, dz = paz - pbz;
            const float d  = sqrtf(fmaf(dx, dx, fmaf(dy, dy, dz * dz)));
            #pragma unroll
            for (int j4 = 0; j4 < 4; j4++) {
                const int   j = q * 4 + j4;
                const float u = (d - 0.4f * (float)j) * 2.6666666667f;
                sRT[buf][j][el] = __expf(-u * u);
            }
        }
        // ---- prefetch: pos for tile+stride, idx for tile+2*stride ----
        {
            pax = pos[3 * ia2]; pay = pos[3 * ia2 + 1]; paz = pos[3 * ia2 + 2];
            pbx = pos[3 * ib2]; pby = pos[3 * ib2 + 1]; pbz = pos[3 * ib2 + 2];
            int ge2 = (int)min((tile + 2 * stride) * E_TILE + el, (long long)n_edges - 1);
            ia2 = edge_index[ge2];
            ib2 = edge_index[n_edges + ge2];
        }
        __syncthreads();

        // ---- phase 2: 8 edge-pairs per warp, packed (edge_a, edge_b) math ----
        const int e0 = (int)(tile * E_TILE);
        #pragma unroll
        for (int p = 0; p < 8; p++) {
            const int elx = pg * 16 + 2 * p;         // local edge a (even)
            const int ea  = e0 + elx;

            // (r_a, r_b) packed multiplicands via 8B broadcast loads
            const float* rb = &sRT[buf][0][elx];
            unsigned long long a0 = bd0, a1 = bd1;
            #pragma unroll
            for (int k = 0; k < DC; k++) {
                const unsigned long long rr =
                    *reinterpret_cast<const unsigned long long*>(rb + k * E_PAD);
                a0 = fma2(rr, wd[2 * k],     a0);
                a1 = fma2(rr, wd[2 * k + 1], a1);
            }

            float xa0, xb0, xa1, xb1;
            unpack2(a0, xa0, xb0);     // col c   : edges a, b
            unpack2(a1, xa1, xb1);     // col c+1 : edges a, b

            const float2 oa = make_float2(fast_sigmoid(xa0), fast_sigmoid(xa1));
            const float2 ob = make_float2(fast_sigmoid(xb0), fast_sigmoid(xb1));

            if (ea < n_edges)
                __stcs(reinterpret_cast<float2*>(out + (size_t)ea * HID + c), oa);
            if (ea + 1 < n_edges)
                __stcs(reinterpret_cast<float2*>(out + (size_t)(ea + 1) * HID + c), ob);
        }
        buf ^= 1;
    }
}

extern "C" void kernel_launch(void* const* d_in, const int* in_sizes, int n_in,
                              void* d_out, int out_size)
{
    const float* pos = (const float*)d_in[0];
    const int*   ei  = (const int*)d_in[1];
    const float* W   = (const float*)d_in[2];
    const float* b   = (const float*)d_in[3];
    float*       out = (float*)d_out;

    const int n_edges = out_size / HID;
    const int n_tiles = (n_edges + E_TILE - 1) / E_TILE;
    int blocks = 148 * 12;                   // persistent grid (3 blocks/SM target)
    if (blocks > n_tiles) blocks = n_tiles;

    edge_attr_kernel<<<blocks, THREADS>>>(pos, ei, W, b, out, n_edges, n_tiles);
}

// round 10
// speedup vs baseline: 1.1272x; 1.1272x over previous
#include <cuda_runtime.h>
#include <math.h>

// EdgeAttr: out[e][c] = sigmoid( sum_k exp(-(((d_e - 0.4k)/0.375)^2)) * W[k][c] + b[c] )
// Inputs: pos [N,3] f32, edge_index [2,E] int32, W [16,128] f32, b [128] f32
// Output: [E,128] f32
//
// R9: R5 skeleton; rbf row stored duplicated (r,r) per k; phase 2 consumes it via
//     explicit ld.shared.v2.b64 -> two packed f32x2 multiplicands per LDS.128,
//     feeding fma.rn.f32x2 with no pack MOVs. W in regs; ex2/rcp sigmoid;
//     persistent grid; double buffer; 2-deep gather pipeline; float4 streaming stores.

#define THREADS 256
#define E_TILE  64
#define HID     128
#define DC      16

__device__ __forceinline__ unsigned long long pack2(float lo, float hi) {
    unsigned long long r;
    asm("mov.b64 %0, {%1, %2};" : "=l"(r) : "f"(lo), "f"(hi));
    return r;
}
__device__ __forceinline__ void unpack2(unsigned long long v, float& lo, float& hi) {
    asm("mov.b64 {%0, %1}, %2;" : "=f"(lo), "=f"(hi) : "l"(v));
}
__device__ __forceinline__ unsigned long long fma2(unsigned long long a,
                                                   unsigned long long b,
                                                   unsigned long long c) {
    unsigned long long d;
    asm("fma.rn.f32x2 %0, %1, %2, %3;" : "=l"(d) : "l"(a), "l"(b), "l"(c));
    return d;
}
__device__ __forceinline__ float fast_sigmoid(float x) {
    // 1 / (1 + 2^(-x*log2e)) : 2 MUFU + 1 FMUL + 1 FADD  (proven)
    float e, r;
    asm("ex2.approx.f32 %0, %1;" : "=f"(e) : "f"(-1.4426950408889634f * x));
    asm("rcp.approx.f32 %0, %1;" : "=f"(r) : "f"(1.0f + e));
    return r;
}

__global__ __launch_bounds__(THREADS, 2)
void edge_attr_kernel(const float* __restrict__ pos,
                      const int* __restrict__ edge_index,
                      const float* __restrict__ W,
                      const float* __restrict__ bias,
                      float* __restrict__ out,
                      int n_edges, int n_tiles)
{
    // RBF tile, duplicated per k: sR[buf][edge][k] = (r_k, r_k) as b64.  16 KB.
    __shared__ __align__(16) unsigned long long sR[2][E_TILE][DC];

    const int t    = threadIdx.x;
    const int lane = t & 31;
    const int w    = t >> 5;
    const int c    = lane * 4;            // this lane's 4 output columns

    // ---- W slice + bias into registers (once per block) ----
    unsigned long long wreg[2 * DC];      // wreg[2k]=(W[k][c],W[k][c+1]), wreg[2k+1]=(c+2,c+3)
    #pragma unroll
    for (int kk = 0; kk < DC; kk++) {
        const float4 wv = *reinterpret_cast<const float4*>(W + kk * HID + c);
        wreg[2 * kk]     = pack2(wv.x, wv.y);
        wreg[2 * kk + 1] = pack2(wv.z, wv.w);
    }
    unsigned long long b01, b23;
    {
        const float4 bv = *reinterpret_cast<const float4*>(bias + c);
        b01 = pack2(bv.x, bv.y);
        b23 = pack2(bv.z, bv.w);
    }

    // Phase-1 role: 4 threads per edge, each computes 4 RBF terms
    const int el = t >> 2;                // local edge 0..63
    const int q  = t & 3;                 // quarter 0..3
    const long long stride = gridDim.x;

    // ---- gather pipeline registers (2-deep: idx one tile ahead of pos) ----
    int   ia2, ib2;
    float pax, pay, paz, pbx, pby, pbz;

    long long tile = blockIdx.x;
    {   // prologue: pos for tile, idx for tile+stride
        int ge = (int)min(tile * E_TILE + el, (long long)n_edges - 1);
        const int ia = edge_index[ge];
        const int ib = edge_index[n_edges + ge];
        pax = pos[3 * ia]; pay = pos[3 * ia + 1]; paz = pos[3 * ia + 2];
        pbx = pos[3 * ib]; pby = pos[3 * ib + 1]; pbz = pos[3 * ib + 2];
        int ge2 = (int)min((tile + stride) * E_TILE + el, (long long)n_edges - 1);
        ia2 = edge_index[ge2];
        ib2 = edge_index[n_edges + ge2];
    }

    int buf = 0;
    for (; tile < n_tiles; tile += stride) {
        // ---- phase 1: RBF for current tile, stored duplicated (r,r) ----
        {
            const float dx = pax - pbx, dy = pay - pby, dz = paz - pbz;
            const float d  = sqrtf(fmaf(dx, dx, fmaf(dy, dy, dz * dz)));
            float r[4];
            #pragma unroll
            for (int j4 = 0; j4 < 4; j4++) {
                const float u = (d - 0.4f * (float)(q * 4 + j4)) * 2.6666666667f;
                r[j4] = __expf(-u * u);
            }
            float4* dst = reinterpret_cast<float4*>(&sR[buf][el][q * 4]);
            dst[0] = make_float4(r[0], r[0], r[1], r[1]);   // 16B STS
            dst[1] = make_float4(r[2], r[2], r[3], r[3]);   // 16B STS
        }
        // ---- prefetch: pos for tile+stride, idx for tile+2*stride ----
        {
            pax = pos[3 * ia2]; pay = pos[3 * ia2 + 1]; paz = pos[3 * ia2 + 2];
            pbx = pos[3 * ib2]; pby = pos[3 * ib2 + 1]; pbz = pos[3 * ib2 + 2];
            int ge2 = (int)min((tile + 2 * stride) * E_TILE + el, (long long)n_edges - 1);
            ia2 = edge_index[ge2];
            ib2 = edge_index[n_edges + ge2];
        }
        __syncthreads();

        // ---- phase 2: matvec, packed multiplicands straight from LDS.128 ----
        const int e0 = (int)(tile * E_TILE);
        #pragma unroll
        for (int k = 0; k < 8; k++) {
            const int elx = (w << 3) + k;
            const int ge  = e0 + elx;

            const unsigned int sb =
                (unsigned int)__cvta_generic_to_shared(&sR[buf][elx][0]);

            unsigned long long a0 = b01, a1 = b23;
            #pragma unroll
            for (int kq = 0; kq < 8; kq++) {
                unsigned long long r0, r1;   // (r_{2kq},r_{2kq}), (r_{2kq+1},r_{2kq+1})
                asm volatile("ld.shared.v2.b64 {%0, %1}, [%2];"
                             : "=l"(r0), "=l"(r1) : "r"(sb + kq * 16));
                a0 = fma2(r0, wreg[4 * kq + 0], a0);
                a1 = fma2(r0, wreg[4 * kq + 1], a1);
                a0 = fma2(r1, wreg[4 * kq + 2], a0);
                a1 = fma2(r1, wreg[4 * kq + 3], a1);
            }

            float x0, x1, x2, x3;
            unpack2(a0, x0, x1);
            unpack2(a1, x2, x3);
            const float4 o = make_float4(fast_sigmoid(x0), fast_sigmoid(x1),
                                         fast_sigmoid(x2), fast_sigmoid(x3));
            if (ge < n_edges)
                __stcs(reinterpret_cast<float4*>(out + (size_t)ge * HID + c), o);
        }
        buf ^= 1;
    }
}

extern "C" void kernel_launch(void* const* d_in, const int* in_sizes, int n_in,
                              void* d_out, int out_size)
{
    const float* pos = (const float*)d_in[0];
    const int*   ei  = (const int*)d_in[1];
    const float* W   = (const float*)d_in[2];
    const float* b   = (const float*)d_in[3];
    float*       out = (float*)d_out;

    const int n_edges = out_size / HID;
    const int n_tiles = (n_edges + E_TILE - 1) / E_TILE;
    int blocks = 148 * 8;                    // persistent grid
    if (blocks > n_tiles) blocks = n_tiles;

    edge_attr_kernel<<<blocks, THREADS>>>(pos, ei, W, b, out, n_edges, n_tiles);
}

// round 13
// speedup vs baseline: 1.1375x; 1.0091x over previous
#include <cuda_runtime.h>
#include <math.h>

// EdgeAttr: out[e][c] = sigmoid( sum_k exp(-(((d_e - 0.4k)/0.375)^2)) * W[k][c] + b[c] )
// Inputs: pos [N,3] f32, edge_index [2,E] int32, W [16,128] f32, b [128] f32
// Output: [E,128] f32
//
// R10: horizontal f32x2 accumulation. Multiplicand pairs (r_2j, r_2j+1) come packed
//      for free from ld.shared.v2.b64 on the plain contiguous rbf row (R5 layout);
//      W pre-packed as (W[2j][c], W[2j+1][c]) in regs; accumulator per column is
//      (even-k sum, odd-k sum), horizontally reduced at the end with bias folded in.
//      Zero pack MOVs in the hot loop. ex2/rcp sigmoid; persistent grid; double
//      buffer; 2-deep gather pipeline; float4 streaming stores.

#define THREADS 256
#define E_TILE  64
#define HID     128
#define DC      16

__device__ __forceinline__ unsigned long long pack2(float lo, float hi) {
    unsigned long long r;
    asm("mov.b64 %0, {%1, %2};" : "=l"(r) : "f"(lo), "f"(hi));
    return r;
}
__device__ __forceinline__ void unpack2(unsigned long long v, float& lo, float& hi) {
    asm("mov.b64 {%0, %1}, %2;" : "=f"(lo), "=f"(hi) : "l"(v));
}
__device__ __forceinline__ unsigned long long fma2(unsigned long long a,
                                                   unsigned long long b,
                                                   unsigned long long c) {
    unsigned long long d;
    asm("fma.rn.f32x2 %0, %1, %2, %3;" : "=l"(d) : "l"(a), "l"(b), "l"(c));
    return d;
}
__device__ __forceinline__ float fast_sigmoid(float x) {
    // 1 / (1 + 2^(-x*log2e)) : 2 MUFU + 1 FMUL + 1 FADD  (proven)
    float e, r;
    asm("ex2.approx.f32 %0, %1;" : "=f"(e) : "f"(-1.4426950408889634f * x));
    asm("rcp.approx.f32 %0, %1;" : "=f"(r) : "f"(1.0f + e));
    return r;
}

__global__ __launch_bounds__(THREADS, 2)
void edge_attr_kernel(const float* __restrict__ pos,
                      const int* __restrict__ edge_index,
                      const float* __restrict__ W,
                      const float* __restrict__ bias,
                      float* __restrict__ out,
                      int n_edges, int n_tiles)
{
    // Plain contiguous RBF tile (R5 layout): sR[buf][edge][k], 64 B per edge.  8 KB.
    __shared__ __align__(16) float sR[2][E_TILE][DC];

    const int t    = threadIdx.x;
    const int lane = t & 31;
    const int w    = t >> 5;
    const int c    = lane * 4;            // this lane's 4 output columns

    // ---- W packed by k-pairs: wreg[4*j+col] = (W[2j][c+col], W[2j+1][c+col]) ----
    unsigned long long wreg[2 * DC];      // 8 pairs x 4 cols = 32 b64 = 64 regs
    #pragma unroll
    for (int j = 0; j < DC / 2; j++) {
        const float4 w0 = *reinterpret_cast<const float4*>(W + (2 * j)     * HID + c);
        const float4 w1 = *reinterpret_cast<const float4*>(W + (2 * j + 1) * HID + c);
        wreg[4 * j + 0] = pack2(w0.x, w1.x);
        wreg[4 * j + 1] = pack2(w0.y, w1.y);
        wreg[4 * j + 2] = pack2(w0.z, w1.z);
        wreg[4 * j + 3] = pack2(w0.w, w1.w);
    }
    // bias folded into accumulator init: (b_c, 0)
    unsigned long long binit[4];
    {
        const float4 bv = *reinterpret_cast<const float4*>(bias + c);
        binit[0] = pack2(bv.x, 0.0f);
        binit[1] = pack2(bv.y, 0.0f);
        binit[2] = pack2(bv.z, 0.0f);
        binit[3] = pack2(bv.w, 0.0f);
    }

    // Phase-1 role: 4 threads per edge, each computes 4 RBF terms
    const int el = t >> 2;                // local edge 0..63
    const int q  = t & 3;                 // quarter 0..3
    const int stride = gridDim.x;

    // ---- gather pipeline registers (2-deep: idx one tile ahead of pos) ----
    int   ia2, ib2;
    float pax, pay, paz, pbx, pby, pbz;

    int tile = blockIdx.x;
    {   // prologue: pos for tile, idx for tile+stride
        int ge = min(tile * E_TILE + el, n_edges - 1);
        const int ia = edge_index[ge];
        const int ib = edge_index[n_edges + ge];
        pax = pos[3 * ia]; pay = pos[3 * ia + 1]; paz = pos[3 * ia + 2];
        pbx = pos[3 * ib]; pby = pos[3 * ib + 1]; pbz = pos[3 * ib + 2];
        int ge2 = min((tile + stride) * E_TILE + el, n_edges - 1);
        ia2 = edge_index[ge2];
        ib2 = edge_index[n_edges + ge2];
    }

    int buf = 0;
    for (; tile < n_tiles; tile += stride) {
        // ---- phase 1: RBF for current tile (one STS.128 per thread) ----
        {
            const float dx = pax - pbx, dy = pay - pby, dz = paz - pbz;
            const float d  = sqrtf(fmaf(dx, dx, fmaf(dy, dy, dz * dz)));
            float r[4];
            #pragma unroll
            for (int j4 = 0; j4 < 4; j4++) {
                const float u = (d - 0.4f * (float)(q * 4 + j4)) * 2.6666666667f;
                r[j4] = __expf(-u * u);
            }
            *reinterpret_cast<float4*>(&sR[buf][el][q * 4]) =
                make_float4(r[0], r[1], r[2], r[3]);
        }
        // ---- prefetch: pos for tile+stride, idx for tile+2*stride ----
        {
            pax = pos[3 * ia2]; pay = pos[3 * ia2 + 1]; paz = pos[3 * ia2 + 2];
            pbx = pos[3 * ib2]; pby = pos[3 * ib2 + 1]; pbz = pos[3 * ib2 + 2];
            int ge2 = min((tile + 2 * stride) * E_TILE + el, n_edges - 1);
            ia2 = edge_index[ge2];
            ib2 = edge_index[n_edges + ge2];
        }
        __syncthreads();

        // ---- phase 2: matvec with horizontal f32x2 accumulation ----
        const int e0 = tile * E_TILE;
        #pragma unroll
        for (int k = 0; k < 8; k++) {
            const int elx = (w << 3) + k;
            const int ge  = e0 + elx;

            const unsigned int sb =
                (unsigned int)__cvta_generic_to_shared(&sR[buf][elx][0]);

            unsigned long long a0 = binit[0], a1 = binit[1];
            unsigned long long a2 = binit[2], a3 = binit[3];
            #pragma unroll
            for (int j = 0; j < 4; j++) {
                unsigned long long p, qq;   // (r_{4j},r_{4j+1}), (r_{4j+2},r_{4j+3})
                asm volatile("ld.shared.v2.b64 {%0, %1}, [%2];"
                             : "=l"(p), "=l"(qq) : "r"(sb + j * 16));
                a0 = fma2(p,  wreg[8 * j + 0], a0);
                a1 = fma2(p,  wreg[8 * j + 1], a1);
                a2 = fma2(p,  wreg[8 * j + 2], a2);
                a3 = fma2(p,  wreg[8 * j + 3], a3);
                a0 = fma2(qq, wreg[8 * j + 4], a0);
                a1 = fma2(qq, wreg[8 * j + 5], a1);
                a2 = fma2(qq, wreg[8 * j + 6], a2);
                a3 = fma2(qq, wreg[8 * j + 7], a3);
            }

            // horizontal reduce (even+odd) then sigmoid
            float lo, hi, x0, x1, x2, x3;
            unpack2(a0, lo, hi); x0 = lo + hi;
            unpack2(a1, lo, hi); x1 = lo + hi;
            unpack2(a2, lo, hi); x2 = lo + hi;
            unpack2(a3, lo, hi); x3 = lo + hi;
            const float4 o = make_float4(fast_sigmoid(x0), fast_sigmoid(x1),
                                         fast_sigmoid(x2), fast_sigmoid(x3));
            if (ge < n_edges)
                __stcs(reinterpret_cast<float4*>(out + (size_t)ge * HID + c), o);
        }
        buf ^= 1;
    }
}

extern "C" void kernel_launch(void* const* d_in, const int* in_sizes, int n_in,
                              void* d_out, int out_size)
{
    const float* pos = (const float*)d_in[0];
    const int*   ei  = (const int*)d_in[1];
    const float* W   = (const float*)d_in[2];
    const float* b   = (const float*)d_in[3];
    float*       out = (float*)d_out;

    const int n_edges = out_size / HID;
    const int n_tiles = (n_edges + E_TILE - 1) / E_TILE;
    int blocks = 148 * 8;                    // persistent grid
    if (blocks > n_tiles) blocks = n_tiles;

    edge_attr_kernel<<<blocks, THREADS>>>(pos, ei, W, b, out, n_edges, n_tiles);
}